// round 2
// baseline (speedup 1.0000x reference)
#include <cuda_runtime.h>
#include <math.h>
#include <stdint.h>

#define BATCH   8
#define CIN     64
#define COUT    64
#define NCO     256
#define T_LEN   16384
#define TILE    64
#define NTILES  (T_LEN / TILE)   // 256

// ---------------- scratch (device globals: no cudaMalloc allowed) ----------
__device__ float  g_u[(size_t)BATCH * NCO * T_LEN];   // 134 MB  u[b][n][t]
__device__ float2 g_lam[NCO];                         // lambda per coeff
__device__ float2 g_lamL[NCO];                        // lambda^TILE (double-accurate)
__device__ float  g_bhT[CIN * NCO];                   // B_hat transposed [c][n]
__device__ float2 g_zend[(size_t)BATCH * NCO * NTILES];
__device__ float2 g_zstart[(size_t)BATCH * NCO * NTILES];

// ---------------- packed fp32x2 helpers (sm_100+) --------------------------
__device__ __forceinline__ void fma2(unsigned long long& acc,
                                     unsigned long long a, unsigned long long b) {
    asm("fma.rn.f32x2 %0, %1, %2, %0;" : "+l"(acc) : "l"(a), "l"(b));
}
__device__ __forceinline__ unsigned long long bcast2(float w) {
    unsigned long long r;
    asm("mov.b64 %0, {%1, %1};" : "=l"(r) : "f"(w));
    return r;
}
__device__ __forceinline__ float2 unpack2(unsigned long long v) {
    float2 f;
    asm("mov.b64 {%0, %1}, %2;" : "=f"(f.x), "=f"(f.y) : "l"(v));
    return f;
}

// ---------------- kernel P: per-coefficient precompute ---------------------
__global__ void kP(const float* __restrict__ A, const float* __restrict__ Bm,
                   const float* __restrict__ log_dt) {
    int n = threadIdx.x;              // 256 threads, one per coeff
    double la = (double)A[2 * n];
    double ai = (double)A[2 * n + 1];
    double dt = exp((double)log_dt[n]);
    double sp = log1p(exp(la));       // softplus
    double re = -dt * sp;
    double im =  dt * ai;
    double er = exp(re);
    g_lam[n]  = make_float2((float)(er * cos(im)), (float)(er * sin(im)));
    double erL = exp(re * (double)TILE);
    double imL = im * (double)TILE;
    g_lamL[n] = make_float2((float)(erL * cos(imL)), (float)(erL * sin(imL)));
    float dtf = (float)dt;
    for (int c = 0; c < CIN; c++)
        g_bhT[c * NCO + n] = Bm[n * CIN + c] * dtf;
}

// ---------------- kernel A: u = B_hat @ x  (+ fused pass-1 scan) -----------
// block = (tile, b), 256 threads. Thread owns coeff n = tid, accumulates all
// 64 t of the tile in packed f32x2 registers; x read via broadcast LDS.128.
#define BHT_PAD 260                   // 64*260 = 16640 = 256*65 (reused as us)
#define SMEM_A  ((CIN * TILE + CIN * BHT_PAD) * 4)

extern __shared__ float s_dyn[];

__global__ void __launch_bounds__(256, 2) kA(const float* __restrict__ x) {
    float* xs = s_dyn;                        // [c][t]  64*64
    float* bh = s_dyn + CIN * TILE;           // [c][n]  64*260 (padded)
    int b = blockIdx.y, tile = blockIdx.x;
    int tid = threadIdx.x;
    size_t t0 = (size_t)tile * TILE;

    for (int idx = tid; idx < CIN * TILE; idx += 256) {
        int c = idx >> 6, t = idx & 63;
        xs[c * TILE + t] = x[((size_t)(b * CIN + c)) * T_LEN + t0 + t];
    }
    for (int idx = tid; idx < CIN * NCO; idx += 256) {
        int c = idx >> 8, n = idx & 255;
        bh[c * BHT_PAD + n] = g_bhT[idx];
    }
    __syncthreads();

    int n = tid;
    unsigned long long acc2[TILE / 2];
#pragma unroll
    for (int i = 0; i < TILE / 2; i++) acc2[i] = 0ULL;

    for (int c = 0; c < CIN; c++) {
        unsigned long long w2 = bcast2(bh[c * BHT_PAD + n]); // lane-consecutive
#pragma unroll
        for (int q = 0; q < TILE / 4; q++) {  // broadcast LDS.128
            ulonglong2 xv = *(const ulonglong2*)&xs[c * TILE + q * 4];
            fma2(acc2[2 * q + 0], w2, xv.x);
            fma2(acc2[2 * q + 1], w2, xv.y);
        }
    }

    // pass-1: chunk-local complex recurrence with zero init (in registers)
    float2 lam = g_lam[n];
    float zr = 0.f, zi = 0.f;
#pragma unroll
    for (int p = 0; p < TILE / 2; p++) {
        float2 u2 = unpack2(acc2[p]);
        float nr = fmaf(lam.x, zr, fmaf(-lam.y, zi, u2.x));
        float ni = fmaf(lam.x, zi, lam.y * zr);
        zr = nr; zi = ni;
        nr = fmaf(lam.x, zr, fmaf(-lam.y, zi, u2.y));
        ni = fmaf(lam.x, zi, lam.y * zr);
        zr = nr; zi = ni;
    }
    g_zend[((size_t)(b * NCO + n)) * NTILES + tile] = make_float2(zr, zi);

    // stage u through smem (reuse bh) for coalesced global writes
    __syncthreads();
    float* us = bh;                           // [n][65]
#pragma unroll
    for (int p = 0; p < TILE / 2; p++) {
        float2 u2 = unpack2(acc2[p]);
        us[n * 65 + 2 * p]     = u2.x;
        us[n * 65 + 2 * p + 1] = u2.y;
    }
    __syncthreads();
    for (int idx = tid; idx < NCO * TILE; idx += 256) {
        int nn = idx >> 6, t = idx & 63;
        g_u[((size_t)(b * NCO + nn)) * T_LEN + t0 + t] = us[nn * 65 + t];
    }
}

// ---------------- kernel B: cross-chunk scan (tiny) ------------------------
__global__ void kB() {
    int b = blockIdx.x, n = threadIdx.x;
    float2 lamL = g_lamL[n];
    float cr = 0.f, ci = 0.f;
    size_t base = ((size_t)(b * NCO + n)) * NTILES;
    for (int j = 0; j < NTILES; j++) {
        float2 ze = g_zend[base + j];
        g_zstart[base + j] = make_float2(cr, ci);   // state entering chunk j
        float nr = fmaf(lamL.x, cr, fmaf(-lamL.y, ci, ze.x));
        float ni = fmaf(lamL.x, ci, fmaf( lamL.y, cr, ze.y));
        cr = nr; ci = ni;
    }
}

// ---------------- kernel C: pass-2 replay + y = C @ v ----------------------
#define USP 68                        // 64 + 4 pad: float4 align, limits conflicts
#define CTP 64                        // lanes read consecutive d -> conflict-free
#define SMEM_C ((NCO * USP + NCO * CTP) * 4)

__global__ void __launch_bounds__(256) kC(const float* __restrict__ Cm,
                                          float* __restrict__ out) {
    float* us = s_dyn;                        // [n][68]
    float* ct = s_dyn + NCO * USP;            // [n][64]  (C transposed)
    int b = blockIdx.y, tile = blockIdx.x;
    int tid = threadIdx.x;
    size_t t0 = (size_t)tile * TILE;

    for (int idx = tid; idx < NCO * TILE; idx += 256) {
        int n = idx >> 6, t = idx & 63;
        us[n * USP + t] = g_u[((size_t)(b * NCO + n)) * T_LEN + t0 + t];
    }
    for (int idx = tid; idx < COUT * NCO; idx += 256) {
        int d = idx >> 8, n = idx & 255;      // C row-major [d][n], coalesced read
        ct[n * CTP + d] = Cm[idx];
    }
    __syncthreads();

    // pass-2: replay recurrence with correct initial state, v = Re(z) in place
    {
        int n = tid;
        float2 lam = g_lam[n];
        float2 zs = g_zstart[((size_t)(b * NCO + n)) * NTILES + tile];
        float zr = zs.x, zi = zs.y;
#pragma unroll
        for (int i = 0; i < TILE; i++) {
            float uv = us[n * USP + i];
            float nr = fmaf(lam.x, zr, fmaf(-lam.y, zi, uv));
            float ni = fmaf(lam.x, zi, lam.y * zr);
            zr = nr; zi = ni;
            us[n * USP + i] = zr;             // overwrite u with v
        }
    }
    __syncthreads();

    // GEMM2: y[d][t] = sum_n ct[n][d] * v[n][t]; thread = (d, 16-t group)
    int d  = tid & 63;
    int tb = (tid >> 6) * 16;
    unsigned long long acc2[8];
#pragma unroll
    for (int i = 0; i < 8; i++) acc2[i] = 0ULL;

    for (int n = 0; n < NCO; n++) {
        unsigned long long cw2 = bcast2(ct[n * CTP + d]);  // lane-consecutive
#pragma unroll
        for (int q = 0; q < 4; q++) {         // broadcast LDS.128
            ulonglong2 v = *(const ulonglong2*)&us[n * USP + tb + q * 4];
            fma2(acc2[2 * q + 0], cw2, v.x);
            fma2(acc2[2 * q + 1], cw2, v.y);
        }
    }
    __syncthreads();
#pragma unroll
    for (int p = 0; p < 8; p++) {
        float2 a = unpack2(acc2[p]);
        us[d * USP + tb + 2 * p]     = a.x;
        us[d * USP + tb + 2 * p + 1] = a.y;
    }
    __syncthreads();
    for (int idx = tid; idx < COUT * TILE; idx += 256) {
        int dd = idx >> 6, t = idx & 63;
        out[((size_t)(b * COUT + dd)) * T_LEN + t0 + t] = us[dd * USP + t];
    }
}

// ---------------- launch ----------------------------------------------------
extern "C" void kernel_launch(void* const* d_in, const int* in_sizes, int n_in,
                              void* d_out, int out_size) {
    const float* x   = (const float*)d_in[0];  // (8, 64, 16384)
    const float* A   = (const float*)d_in[1];  // (256, 2)
    const float* Bm  = (const float*)d_in[2];  // (256, 64)
    const float* ldt = (const float*)d_in[3];  // (256,)
    const float* Cm  = (const float*)d_in[4];  // (64, 256)
    float* y = (float*)d_out;                  // (8, 64, 16384)

    cudaFuncSetAttribute(kA, cudaFuncAttributeMaxDynamicSharedMemorySize, SMEM_A);
    cudaFuncSetAttribute(kC, cudaFuncAttributeMaxDynamicSharedMemorySize, SMEM_C);

    kP<<<1, 256>>>(A, Bm, ldt);
    kA<<<dim3(NTILES, BATCH), 256, SMEM_A>>>(x);
    kB<<<BATCH, 256>>>();
    kC<<<dim3(NTILES, BATCH), 256, SMEM_C>>>(Cm, y);
}

// round 4
// speedup vs baseline: 1.2642x; 1.2642x over previous
#include <cuda_runtime.h>
#include <math.h>
#include <stdint.h>

#define BATCH   8
#define CIN     64
#define COUT    64
#define NCO     256
#define T_LEN   16384
#define CHUNK   32
#define NCH     (T_LEN / CHUNK)      // 512

// ---------------- scratch (device globals: no cudaMalloc allowed) ----------
__device__ float  g_u[(size_t)BATCH * NCO * T_LEN];   // 134 MB  u[b][n][t]
__device__ float2 g_lam[NCO];                         // lambda per coeff
__device__ float2 g_lamL[NCO];                        // lambda^CHUNK (dbl-accurate)
__device__ float  g_bhT[CIN * NCO];                   // B_hat transposed [c][n]
__device__ float  g_ctT[NCO * COUT];                  // C transposed [n][d]
__device__ float2 g_zend[(size_t)BATCH * NCO * NCH];
__device__ float2 g_zstart[(size_t)BATCH * NCO * NCH];

// ---------------- packed fp32x2 helpers (sm_100+) --------------------------
__device__ __forceinline__ void fma2(unsigned long long& acc,
                                     unsigned long long a, unsigned long long b) {
    asm("fma.rn.f32x2 %0, %1, %2, %0;" : "+l"(acc) : "l"(a), "l"(b));
}
__device__ __forceinline__ unsigned long long bcast2(float w) {
    unsigned long long r;
    asm("mov.b64 %0, {%1, %1};" : "=l"(r) : "f"(w));
    return r;
}

// ---------------- kernel P: per-coefficient precompute ---------------------
__global__ void kP(const float* __restrict__ A, const float* __restrict__ Bm,
                   const float* __restrict__ log_dt, const float* __restrict__ Cm) {
    int n = threadIdx.x;              // 256 threads, one per coeff
    double la = (double)A[2 * n];
    double ai = (double)A[2 * n + 1];
    double dt = exp((double)log_dt[n]);
    double sp = log1p(exp(la));       // softplus
    double re = -dt * sp;
    double im =  dt * ai;
    double er = exp(re);
    g_lam[n]  = make_float2((float)(er * cos(im)), (float)(er * sin(im)));
    double erL = exp(re * (double)CHUNK);
    double imL = im * (double)CHUNK;
    g_lamL[n] = make_float2((float)(erL * cos(imL)), (float)(erL * sin(imL)));
    float dtf = (float)dt;
    for (int c = 0; c < CIN; c++)
        g_bhT[c * NCO + n] = Bm[n * CIN + c] * dtf;
    for (int d = 0; d < COUT; d++)
        g_ctT[n * COUT + d] = Cm[d * NCO + n];
}

// ---------------- kernel A: u = B_hat @ x  (+ fused pass-1 scan) -----------
// CTA = (t-tile of 64, b), 512 threads. Thread = (n = tid&255, thalf = tid>>8),
// owns 32 t in packed f32x2 regs. x tile in smem; B_hat via L1-hot LDG.
#define TILE_A 64
#define XSP    68

__global__ void __launch_bounds__(512, 2) kA(const float* __restrict__ x) {
    __shared__ float xs[CIN * XSP];           // [c][t]  17.4 KB
    int b = blockIdx.y, tile = blockIdx.x;
    int tid = threadIdx.x;
    size_t t0 = (size_t)tile * TILE_A;

    for (int idx = tid; idx < CIN * TILE_A; idx += 512) {
        int c = idx >> 6, t = idx & 63;
        xs[c * XSP + t] = x[((size_t)(b * CIN + c)) * T_LEN + t0 + t];
    }
    __syncthreads();

    int n     = tid & 255;
    int thalf = tid >> 8;
    int toff  = thalf * 32;

    unsigned long long acc2[16];              // 32 t as 16 f32x2
#pragma unroll
    for (int i = 0; i < 16; i++) acc2[i] = 0ULL;

#pragma unroll 4
    for (int c = 0; c < CIN; c++) {
        unsigned long long w2 = bcast2(__ldg(&g_bhT[c * NCO + n])); // coalesced
        const ulonglong2* xv = (const ulonglong2*)&xs[c * XSP + toff];
#pragma unroll
        for (int q = 0; q < 8; q++) {         // broadcast LDS.128
            ulonglong2 v = xv[q];
            fma2(acc2[2 * q + 0], w2, v.x);
            fma2(acc2[2 * q + 1], w2, v.y);
        }
    }

    // pass-1: chunk-local complex recurrence with zero init (32-step chunk)
    float2 lam = g_lam[n];
    float zr = 0.f, zi = 0.f;
#pragma unroll
    for (int p = 0; p < 16; p++) {
        float2 u2 = *(float2*)&acc2[p];
        float nr = fmaf(lam.x, zr, fmaf(-lam.y, zi, u2.x));
        float ni = fmaf(lam.x, zi, lam.y * zr);
        zr = nr; zi = ni;
        nr = fmaf(lam.x, zr, fmaf(-lam.y, zi, u2.y));
        ni = fmaf(lam.x, zi, lam.y * zr);
        zr = nr; zi = ni;
    }
    int chunk = tile * 2 + thalf;
    g_zend[((size_t)(b * NCO + n)) * NCH + chunk] = make_float2(zr, zi);

    // direct store: 32 consecutive floats = one full 128B line per thread
    float* orow = &g_u[((size_t)(b * NCO + n)) * T_LEN + t0 + toff];
#pragma unroll
    for (int q = 0; q < 8; q++)
        *(ulonglong2*)&orow[4 * q] = make_ulonglong2(acc2[2 * q], acc2[2 * q + 1]);
}

// ---------------- kernel B: cross-chunk scan (tiny) ------------------------
__global__ void kB() {
    int b = blockIdx.x, n = threadIdx.x;
    float2 lamL = g_lamL[n];
    float cr = 0.f, ci = 0.f;
    size_t base = ((size_t)(b * NCO + n)) * NCH;
    for (int j = 0; j < NCH; j++) {
        float2 ze = g_zend[base + j];
        g_zstart[base + j] = make_float2(cr, ci);   // state entering chunk j
        float nr = fmaf(lamL.x, cr, fmaf(-lamL.y, ci, ze.x));
        float ni = fmaf(lamL.x, ci, fmaf( lamL.y, cr, ze.y));
        cr = nr; ci = ni;
    }
}

// ---------------- kernel C: pass-2 replay + y = C @ v ----------------------
// CTA = (t-tile of 128, b), 256 threads. n processed in 4 panels of 64.
// Thread = (dpair = tid&31 -> d0=2*dpair, tg = tid>>5 -> 16 t), accums 2d x 16t.
#define TILE_C 128
#define NP     64
#define UPP    132

__global__ void __launch_bounds__(256, 3) kC(float* __restrict__ out) {
    __shared__ float up[NP * UPP];            // 33.8 KB u/v panel [np][t]
    int b = blockIdx.y, tile = blockIdx.x;
    int tid = threadIdx.x;
    size_t t0 = (size_t)tile * TILE_C;

    int d0   = (tid & 31) * 2;
    int tgof = (tid >> 5) * 16;

    unsigned long long acc2[2][8];            // 2 d x 16 t
#pragma unroll
    for (int r = 0; r < 2; r++)
#pragma unroll
        for (int i = 0; i < 8; i++) acc2[r][i] = 0ULL;

    // replay assignment: np = tid>>2 (0..63), quarter-chunk c4 = tid&3
    int rnp = tid >> 2, rc4 = tid & 3;

    for (int p = 0; p < 4; p++) {
        int n0p = p * NP;
        // load u panel (coalesced float4)
        for (int idx = tid; idx < NP * (TILE_C / 4); idx += 256) {
            int np = idx >> 5, q = idx & 31;
            *(float4*)&up[np * UPP + 4 * q] =
                *(const float4*)&g_u[((size_t)(b * NCO + n0p + np)) * T_LEN + t0 + 4 * q];
        }
        __syncthreads();

        // pass-2 replay: 256 threads = 64 n x 4 chunks of 32, v = Re(z) in place
        {
            float2 lam = g_lam[n0p + rnp];
            int chunk_g = tile * 4 + rc4;
            float2 zs = g_zstart[((size_t)(b * NCO + n0p + rnp)) * NCH + chunk_g];
            float zr = zs.x, zi = zs.y;
            float* row = &up[rnp * UPP + rc4 * 32];
#pragma unroll
            for (int q = 0; q < 8; q++) {
                float4 uv = *(float4*)&row[4 * q];
                float nr, ni;
                nr = fmaf(lam.x, zr, fmaf(-lam.y, zi, uv.x));
                ni = fmaf(lam.x, zi, lam.y * zr); zr = nr; zi = ni; uv.x = zr;
                nr = fmaf(lam.x, zr, fmaf(-lam.y, zi, uv.y));
                ni = fmaf(lam.x, zi, lam.y * zr); zr = nr; zi = ni; uv.y = zr;
                nr = fmaf(lam.x, zr, fmaf(-lam.y, zi, uv.z));
                ni = fmaf(lam.x, zi, lam.y * zr); zr = nr; zi = ni; uv.z = zr;
                nr = fmaf(lam.x, zr, fmaf(-lam.y, zi, uv.w));
                ni = fmaf(lam.x, zi, lam.y * zr); zr = nr; zi = ni; uv.w = zr;
                *(float4*)&row[4 * q] = uv;
            }
        }
        __syncthreads();

        // GEMM: acc[d][t] += ctT[n][d] * v[n][t]
#pragma unroll 2
        for (int nn = 0; nn < NP; nn++) {
            float2 cw = *(const float2*)&g_ctT[(n0p + nn) * COUT + d0]; // coalesced
            unsigned long long wa = bcast2(cw.x);
            unsigned long long wb = bcast2(cw.y);
            const ulonglong2* vv = (const ulonglong2*)&up[nn * UPP + tgof];
#pragma unroll
            for (int q = 0; q < 4; q++) {     // broadcast LDS.128
                ulonglong2 v = vv[q];
                fma2(acc2[0][2 * q + 0], wa, v.x);
                fma2(acc2[0][2 * q + 1], wa, v.y);
                fma2(acc2[1][2 * q + 0], wb, v.x);
                fma2(acc2[1][2 * q + 1], wb, v.y);
            }
        }
        __syncthreads();
    }

    // write y: 2 rows of 16 consecutive floats each
#pragma unroll
    for (int r = 0; r < 2; r++) {
        float* orow = &out[((size_t)(b * COUT + d0 + r)) * T_LEN + t0 + tgof];
#pragma unroll
        for (int q = 0; q < 4; q++)
            *(ulonglong2*)&orow[4 * q] =
                make_ulonglong2(acc2[r][2 * q], acc2[r][2 * q + 1]);
    }
}

// ---------------- launch ----------------------------------------------------
extern "C" void kernel_launch(void* const* d_in, const int* in_sizes, int n_in,
                              void* d_out, int out_size) {
    const float* x   = (const float*)d_in[0];  // (8, 64, 16384)
    const float* A   = (const float*)d_in[1];  // (256, 2)
    const float* Bm  = (const float*)d_in[2];  // (256, 64)
    const float* ldt = (const float*)d_in[3];  // (256,)
    const float* Cm  = (const float*)d_in[4];  // (64, 256)
    float* y = (float*)d_out;                  // (8, 64, 16384)

    kP<<<1, 256>>>(A, Bm, ldt, Cm);
    kA<<<dim3(T_LEN / TILE_A, BATCH), 512>>>(x);
    kB<<<BATCH, 256>>>();
    kC<<<dim3(T_LEN / TILE_C, BATCH), 256>>>(y);
}